// round 3
// baseline (speedup 1.0000x reference)
#include <cuda_runtime.h>

#define NN 100000
#define EE 1600000
#define FH 32

// ---------------- device scratch (static; no allocations) ----------------
__device__ int g_idx64;                            // 1 if edge_index is int64
__device__ __align__(16) int   g_src[EE];          // int32 source indices
__device__ __align__(16) int   g_dst[EE];          // int32 dest indices
__device__ __align__(16) float g_deg[NN];          // degree, then re-used as dinv
__device__ __align__(16) float g_nw[EE];           // per-edge sym-normalized weight
__device__ __align__(16) float g_aggx[NN * FH];    // segment_sum(nw * x[src]) by dst
__device__ __align__(16) float g_aggh[NN * FH];    // segment_sum(nw * H[src]) by dst
__device__ __align__(16) float g_agghr[NN * FH];   // segment_sum(nw * (H*R)[src]) by dst
__device__ __align__(16) float g_Z[NN * FH];       // update gate
__device__ __align__(16) float g_HR[NN * FH];      // H * R

__device__ __forceinline__ void red_add_v4(float* addr, float a, float b, float c, float d) {
    asm volatile("red.global.add.v4.f32 [%0], {%1, %2, %3, %4};"
                 :: "l"(addr), "f"(a), "f"(b), "f"(c), "f"(d)
                 : "memory");
}

// ---------------- kernels ----------------

// Probe edge_index dtype: int64 values are all < NN; int32 data read as u64
// is >= 2^32 unless the odd word is zero (prob ~1e-5 per entry, ^16 total).
__global__ void detect_kernel(const void* ei) {
    const unsigned long long* p = (const unsigned long long*)ei;
    int is64 = 1;
    for (int i = 0; i < 16; i++)
        if (p[i] >= (unsigned long long)NN) is64 = 0;
    g_idx64 = is64;
}

__global__ void zero_kernel() {
    int i = blockIdx.x * blockDim.x + threadIdx.x;
    if (i < NN * FH) {
        g_aggx[i] = 0.f;
        g_aggh[i] = 0.f;
        g_agghr[i] = 0.f;
    }
    if (i < NN) g_deg[i] = 0.f;
}

// Convert indices to int32 arrays and accumulate weighted out-degree.
__global__ void convert_deg_kernel(const void* ei, const float* __restrict__ ew) {
    int e = blockIdx.x * blockDim.x + threadIdx.x;
    if (e >= EE) return;
    int s, d;
    if (g_idx64) {
        const long long* p = (const long long*)ei;
        s = (int)p[e];
        d = (int)p[EE + e];
    } else {
        const int* p = (const int*)ei;
        s = p[e];
        d = p[EE + e];
    }
    g_src[e] = s;
    g_dst[e] = d;
    float w = (s == d) ? 0.f : ew[e];
    if (w != 0.f) atomicAdd(&g_deg[s], w);
}

__global__ void dinv_kernel() {
    int i = blockIdx.x * blockDim.x + threadIdx.x;
    if (i >= NN) return;
    float dg = g_deg[i];
    g_deg[i] = (dg > 0.f) ? rsqrtf(fmaxf(dg, 1e-30f)) : 0.f;
}

__global__ void nw_kernel(const float* __restrict__ ew) {
    int e = blockIdx.x * blockDim.x + threadIdx.x;
    if (e >= EE) return;
    int s = g_src[e];
    int d = g_dst[e];
    float w = (s == d) ? 0.f : ew[e];
    g_nw[e] = w * g_deg[s] * g_deg[d];
}

// Fused scatter of x and H: 8 threads per edge, 4 features each, vectorized red.
__global__ void scatter_xh_kernel(const float* __restrict__ x,
                                  const float* __restrict__ H) {
    unsigned int t = blockIdx.x * blockDim.x + threadIdx.x;
    int e = (int)(t >> 3);
    if (e >= EE) return;
    int f = ((int)t & 7) * 4;
    float w = g_nw[e];
    if (w == 0.f) return;
    int s = g_src[e];
    int d = g_dst[e];
    const float4 xv = *(const float4*)(x + (size_t)s * FH + f);
    red_add_v4(g_aggx + (size_t)d * FH + f, w * xv.x, w * xv.y, w * xv.z, w * xv.w);
    const float4 hv = *(const float4*)(H + (size_t)s * FH + f);
    red_add_v4(g_aggh + (size_t)d * FH + f, w * hv.x, w * hv.y, w * hv.z, w * hv.w);
}

__global__ void scatter_hr_kernel() {
    unsigned int t = blockIdx.x * blockDim.x + threadIdx.x;
    int e = (int)(t >> 3);
    if (e >= EE) return;
    int f = ((int)t & 7) * 4;
    float w = g_nw[e];
    if (w == 0.f) return;
    int s = g_src[e];
    int d = g_dst[e];
    const float4 hv = *(const float4*)(g_HR + (size_t)s * FH + f);
    red_add_v4(g_agghr + (size_t)d * FH + f, w * hv.x, w * hv.y, w * hv.z, w * hv.w);
}

// Gate kernel: computes Z = sigmoid(cheb(x)+cheb(H)) and HR = H * R,
// warp-per-node, weights (with W1 pre-negated) in smem.
__global__ void __launch_bounds__(256) gate_kernel(
    const float* __restrict__ x, const float* __restrict__ H,
    const float* __restrict__ Wxz, const float* __restrict__ bxz,
    const float* __restrict__ Whz, const float* __restrict__ bhz,
    const float* __restrict__ Wxr, const float* __restrict__ bxr,
    const float* __restrict__ Whr, const float* __restrict__ bhr) {
    __shared__ float sW[8 * 1024];
    __shared__ float sbz[32];
    __shared__ float sbr[32];

    const float* mats[4] = {Wxz, Whz, Wxr, Whr};
    for (int i = threadIdx.x; i < 8 * 1024; i += blockDim.x) {
        int m = i >> 10;        // 0..7: [Wxz0,Wxz1, Whz0,Whz1, Wxr0,Wxr1, Whr0,Whr1]
        int r = i & 1023;
        float v = mats[m >> 1][(m & 1) * 1024 + r];
        sW[i] = (m & 1) ? -v : v;   // fold tx1 = -agg into the weight
    }
    if (threadIdx.x < 32) {
        sbz[threadIdx.x] = bxz[threadIdx.x] + bhz[threadIdx.x];
        sbr[threadIdx.x] = bxr[threadIdx.x] + bhr[threadIdx.x];
    }
    __syncthreads();

    int node = blockIdx.x * 8 + (threadIdx.x >> 5);
    if (node >= NN) return;
    int lane = threadIdx.x & 31;
    size_t base = (size_t)node * FH + lane;

    float xv = x[base];
    float hv = H[base];
    float ax = g_aggx[base];
    float ah = g_aggh[base];
    float az = sbz[lane];
    float ar = sbr[lane];

#pragma unroll
    for (int k = 0; k < 32; k++) {
        float xs  = __shfl_sync(0xffffffffu, xv, k);
        float axs = __shfl_sync(0xffffffffu, ax, k);
        float hs  = __shfl_sync(0xffffffffu, hv, k);
        float ahs = __shfl_sync(0xffffffffu, ah, k);
        int o = k * 32 + lane;
        az = fmaf(xs,  sW[o],        az);
        az = fmaf(axs, sW[1024 + o], az);
        az = fmaf(hs,  sW[2048 + o], az);
        az = fmaf(ahs, sW[3072 + o], az);
        ar = fmaf(xs,  sW[4096 + o], ar);
        ar = fmaf(axs, sW[5120 + o], ar);
        ar = fmaf(hs,  sW[6144 + o], ar);
        ar = fmaf(ahs, sW[7168 + o], ar);
    }
    float z = 1.f / (1.f + __expf(-az));
    float r = 1.f / (1.f + __expf(-ar));
    g_Z[base]  = z;
    g_HR[base] = hv * r;
}

// Output kernel: H_tilde = tanh(cheb(x)+cheb(HR)), h = Z*H + (1-Z)*H_tilde,
// out = relu(h) @ lin_w + lin_b. Writes out (N*4) then h (N*32) into d_out.
__global__ void __launch_bounds__(256) out_kernel(
    const float* __restrict__ x, const float* __restrict__ H,
    const float* __restrict__ Wxh, const float* __restrict__ bxh,
    const float* __restrict__ Whh, const float* __restrict__ bhh,
    const float* __restrict__ lw, const float* __restrict__ lb,
    float* __restrict__ out, int out_size) {
    __shared__ float sW[4 * 1024];
    __shared__ float sbh[32];
    __shared__ float slw[128];
    __shared__ float slb[4];

    for (int i = threadIdx.x; i < 4 * 1024; i += blockDim.x) {
        int m = i >> 10;        // 0..3: [Wxh0,Wxh1, Whh0,Whh1]
        int r = i & 1023;
        const float* Wp = (m < 2) ? Wxh : Whh;
        float v = Wp[(m & 1) * 1024 + r];
        sW[i] = (m & 1) ? -v : v;
    }
    if (threadIdx.x < 32) sbh[threadIdx.x] = bxh[threadIdx.x] + bhh[threadIdx.x];
    if (threadIdx.x < 128) slw[threadIdx.x] = lw[threadIdx.x];
    if (threadIdx.x < 4) slb[threadIdx.x] = lb[threadIdx.x];
    __syncthreads();

    int node = blockIdx.x * 8 + (threadIdx.x >> 5);
    if (node >= NN) return;
    int lane = threadIdx.x & 31;
    size_t base = (size_t)node * FH + lane;

    float xv  = x[base];
    float hrv = g_HR[base];
    float ax  = g_aggx[base];
    float ahr = g_agghr[base];
    float a = sbh[lane];

#pragma unroll
    for (int k = 0; k < 32; k++) {
        float xs  = __shfl_sync(0xffffffffu, xv, k);
        float axs = __shfl_sync(0xffffffffu, ax, k);
        float hs  = __shfl_sync(0xffffffffu, hrv, k);
        float ahs = __shfl_sync(0xffffffffu, ahr, k);
        int o = k * 32 + lane;
        a = fmaf(xs,  sW[o],        a);
        a = fmaf(axs, sW[1024 + o], a);
        a = fmaf(hs,  sW[2048 + o], a);
        a = fmaf(ahs, sW[3072 + o], a);
    }
    float ht = tanhf(a);
    float z = g_Z[base];
    float hval = z * H[base] + (1.f - z) * ht;

    // h section: after out section (N*4 floats). Bounded by out_size so a
    // layout mismatch degrades to rel_err info instead of a fault.
    long long hidx = (long long)NN * 4 + (long long)base;
    if (hidx < (long long)out_size) out[hidx] = hval;

    float rh = fmaxf(hval, 0.f);
#pragma unroll
    for (int j = 0; j < 4; j++) {
        float s = rh * slw[lane * 4 + j];
#pragma unroll
        for (int off = 16; off; off >>= 1) s += __shfl_xor_sync(0xffffffffu, s, off);
        if (lane == 0 && (long long)node * 4 + j < (long long)out_size)
            out[(size_t)node * 4 + j] = s + slb[j];
    }
}

// ---------------- launch ----------------
extern "C" void kernel_launch(void* const* d_in, const int* in_sizes, int n_in,
                              void* d_out, int out_size) {
    const float* x   = (const float*)d_in[0];
    const void*  ei  = d_in[1];
    const float* ew  = (const float*)d_in[2];
    const float* H   = (const float*)d_in[3];
    const float* Wxz = (const float*)d_in[4];
    const float* bxz = (const float*)d_in[5];
    const float* Whz = (const float*)d_in[6];
    const float* bhz = (const float*)d_in[7];
    const float* Wxr = (const float*)d_in[8];
    const float* bxr = (const float*)d_in[9];
    const float* Whr = (const float*)d_in[10];
    const float* bhr = (const float*)d_in[11];
    const float* Wxh = (const float*)d_in[12];
    const float* bxh = (const float*)d_in[13];
    const float* Whh = (const float*)d_in[14];
    const float* bhh = (const float*)d_in[15];
    const float* lw  = (const float*)d_in[16];
    const float* lb  = (const float*)d_in[17];
    float* out = (float*)d_out;

    detect_kernel<<<1, 1>>>(ei);
    zero_kernel<<<(NN * FH + 255) / 256, 256>>>();
    convert_deg_kernel<<<(EE + 255) / 256, 256>>>(ei, ew);
    dinv_kernel<<<(NN + 255) / 256, 256>>>();
    nw_kernel<<<(EE + 255) / 256, 256>>>(ew);
    scatter_xh_kernel<<<(EE * 8 + 255) / 256, 256>>>(x, H);
    gate_kernel<<<(NN + 7) / 8, 256>>>(x, H, Wxz, bxz, Whz, bhz, Wxr, bxr, Whr, bhr);
    scatter_hr_kernel<<<(EE * 8 + 255) / 256, 256>>>();
    out_kernel<<<(NN + 7) / 8, 256>>>(x, H, Wxh, bxh, Whh, bhh, lw, lb, out, out_size);
}